// round 1
// baseline (speedup 1.0000x reference)
#include <cuda_runtime.h>
#include <math.h>

#define NB 8
#define NL 1024
#define ND 256
#define NH 8
#define NDH 32
#define NDFF 2048
#define NM (NB*NL)

// ---------------- scratch (device globals: allocation-free) ----------------
__device__ float gQ[NB*NH*NL*NDH];
__device__ float gK[NB*NH*NL*NDH];
__device__ float gV[NB*NH*NL*NDH];
__device__ float gCtx[NM*ND];
__device__ float gH[NM*ND];
__device__ float gFF[(size_t)NM*NDFF];
__device__ float gWc[ND*ND];
__device__ float gBc[ND];
__device__ int   gLen[NB];
__device__ int   gMode;

// ---------------- mask dtype detection + lengths ----------------
// Safe: only reads first NB*NL bytes (minimum possible buffer size).
__global__ void detect_mask_kernel(const unsigned char* __restrict__ mb) {
    __shared__ int flag;
    if (threadIdx.x == 0) flag = 0;
    __syncthreads();
    int f = 0;
    for (int i = threadIdx.x; i < NB*NL; i += blockDim.x)
        if ((i & 3) != 0 && mb[i] != 0) f = 1;
    if (f) atomicOr(&flag, 1);
    __syncthreads();
    if (threadIdx.x == 0) gMode = flag;  // 1 = 1-byte bool, 0 = 4-byte element
}

__global__ void lengths_kernel(const unsigned char* __restrict__ mb) {
    int b = blockIdx.x;
    __shared__ int cnt;
    if (threadIdx.x == 0) cnt = 0;
    __syncthreads();
    int mode = gMode;
    int c = 0;
    for (int i = threadIdx.x; i < NL; i += blockDim.x) {
        int pad;
        if (mode) pad = (mb[b*NL + i] != 0);
        else      pad = (((const int*)mb)[b*NL + i] != 0);
        if (!pad) c++;
    }
    atomicAdd(&cnt, c);
    __syncthreads();
    if (threadIdx.x == 0) gLen[b] = cnt;
}

// ---------------- weight fusion: Wc = proj_w @ out_w, bc = proj_w@out_b + proj_b ----
__global__ void fuse_w_kernel(const float* __restrict__ pw, const float* __restrict__ ow) {
    int i = blockIdx.x, j = threadIdx.x;
    float s = 0.f;
    for (int k = 0; k < ND; k++)
        s = fmaf(pw[i*ND + k], ow[k*ND + j], s);
    gWc[i*ND + j] = s;
}

__global__ void fuse_b_kernel(const float* __restrict__ pw, const float* __restrict__ ob,
                              const float* __restrict__ pb) {
    int i = threadIdx.x;
    float s = pb[i];
    for (int k = 0; k < ND; k++)
        s = fmaf(pw[i*ND + k], ob[k], s);
    gBc[i] = s;
}

// ---------------- SGEMM: C[M,N] = A[M,K] @ Bw[N,K]^T (+ epilogue) ----------------
// EPI 0: qkv scatter (+bias) into gQ/gK/gV [B,H,L,DH]
// EPI 1: C = acc + bias + res
// EPI 2: C = gelu(acc + bias)       (exact erf)
// EPI 3: C = acc + bias + res, padded rows zeroed
__device__ __forceinline__ float gelu_f(float x) {
    return 0.5f * x * (1.f + erff(x * 0.7071067811865475f));
}

template<int EPI>
__global__ __launch_bounds__(256) void sgemm_k(
    const float* __restrict__ A, const float* __restrict__ Bw,
    const float* __restrict__ bias, const float* __restrict__ res,
    float* __restrict__ C, int M, int N, int K)
{
    __shared__ float As[16][128];
    __shared__ float Bs[16][128];
    const int bm = blockIdx.y * 128, bn = blockIdx.x * 128;
    const int tid = threadIdx.x;
    const int tr = tid >> 4, tc = tid & 15;
    const int lr = tid >> 2, lc = (tid & 3) << 2;
    const float* Ap = A + (size_t)(bm + lr) * K + lc;
    const float* Bp = Bw + (size_t)(bn + lr) * K + lc;

    float acc[8][8];
    #pragma unroll
    for (int i = 0; i < 8; i++)
        #pragma unroll
        for (int j = 0; j < 8; j++) acc[i][j] = 0.f;

    for (int k0 = 0; k0 < K; k0 += 16) {
        float4 a0 = *(const float4*)(Ap + k0);
        float4 a1 = *(const float4*)(Ap + (size_t)64 * K + k0);
        float4 b0 = *(const float4*)(Bp + k0);
        float4 b1 = *(const float4*)(Bp + (size_t)64 * K + k0);
        __syncthreads();
        As[lc+0][lr] = a0.x; As[lc+1][lr] = a0.y; As[lc+2][lr] = a0.z; As[lc+3][lr] = a0.w;
        As[lc+0][lr+64] = a1.x; As[lc+1][lr+64] = a1.y; As[lc+2][lr+64] = a1.z; As[lc+3][lr+64] = a1.w;
        Bs[lc+0][lr] = b0.x; Bs[lc+1][lr] = b0.y; Bs[lc+2][lr] = b0.z; Bs[lc+3][lr] = b0.w;
        Bs[lc+0][lr+64] = b1.x; Bs[lc+1][lr+64] = b1.y; Bs[lc+2][lr+64] = b1.z; Bs[lc+3][lr+64] = b1.w;
        __syncthreads();
        #pragma unroll
        for (int kk = 0; kk < 16; kk++) {
            float ar[8], br[8];
            *(float4*)ar     = *(const float4*)&As[kk][tr*8];
            *(float4*)(ar+4) = *(const float4*)&As[kk][tr*8+4];
            *(float4*)br     = *(const float4*)&Bs[kk][tc*8];
            *(float4*)(br+4) = *(const float4*)&Bs[kk][tc*8+4];
            #pragma unroll
            for (int i = 0; i < 8; i++)
                #pragma unroll
                for (int j = 0; j < 8; j++)
                    acc[i][j] = fmaf(ar[i], br[j], acc[i][j]);
        }
    }

    const int n0 = bn + tc * 8;
    #pragma unroll
    for (int i = 0; i < 8; i++) {
        int m = bm + tr * 8 + i;
        if (EPI == 0) {
            #pragma unroll
            for (int j = 0; j < 8; j++) {
                int n = n0 + j;
                float v = acc[i][j] + bias[n];
                int t = n >> 8, d = n & 255, h = d >> 5, dh = d & 31;
                int bb = m >> 10, ll = m & 1023;
                float* dst = (t == 0) ? gQ : ((t == 1) ? gK : gV);
                dst[(((size_t)(bb*NH + h)) * NL + ll) * NDH + dh] = v;
            }
        } else {
            float v[8];
            #pragma unroll
            for (int j = 0; j < 8; j++) {
                v[j] = acc[i][j] + bias[n0 + j];
                if (EPI == 1 || EPI == 3) v[j] += res[(size_t)m * N + n0 + j];
                if (EPI == 2) v[j] = gelu_f(v[j]);
            }
            if (EPI == 3) {
                int bb = m >> 10, ll = m & 1023;
                if (ll >= gLen[bb]) {
                    #pragma unroll
                    for (int j = 0; j < 8; j++) v[j] = 0.f;
                }
            }
            float* cp = C + (size_t)m * N + n0;
            ((float4*)cp)[0] = *(float4*)v;
            ((float4*)cp)[1] = *(float4*)(v + 4);
        }
    }
}

// ---------------- flash attention (fp32, DH=32) ----------------
// Block = 128 q rows for one (b,h). Online softmax over k < s with bias (s-|q-k|)/s.
// Padded q rows computed anyway (finite, harmless) — final epilogue zeroes them.
__global__ __launch_bounds__(128) void attn_kernel() {
    const int tid = threadIdx.x;
    const int bh = blockIdx.y;
    const int b = bh >> 3, h = bh & 7;
    const int q = blockIdx.x * 128 + tid;

    const float* Qp = gQ + (size_t)bh * NL * NDH + (size_t)q * NDH;
    const float* Kp = gK + (size_t)bh * NL * NDH;
    const float* Vp = gV + (size_t)bh * NL * NDH;

    __shared__ float Ks[64 * NDH];
    __shared__ float Vs[64 * NDH];

    float ql[NDH];
    #pragma unroll
    for (int d = 0; d < NDH; d++) ql[d] = Qp[d];

    const int S = gLen[b];
    const float sf = (float)S;
    const float invs = 1.f / sf;
    const float scale = 0.1767766952966369f;  // 1/sqrt(32)
    const float qf = (float)q;

    float m = -1e30f, l = 0.f;
    float acc[NDH];
    #pragma unroll
    for (int d = 0; d < NDH; d++) acc[d] = 0.f;

    for (int kt = 0; kt < S; kt += 64) {
        __syncthreads();
        const float4* Kg = (const float4*)(Kp + (size_t)kt * NDH);
        const float4* Vg = (const float4*)(Vp + (size_t)kt * NDH);
        #pragma unroll
        for (int i = 0; i < 4; i++) {
            ((float4*)Ks)[tid + i * 128] = Kg[tid + i * 128];
            ((float4*)Vs)[tid + i * 128] = Vg[tid + i * 128];
        }
        __syncthreads();
        const int kmax = min(64, S - kt);
        for (int kk = 0; kk < kmax; kk++) {
            const float4* kr = (const float4*)(Ks + kk * NDH);
            float x = 0.f;
            #pragma unroll
            for (int c = 0; c < 8; c++) {
                float4 kv = kr[c];
                x = fmaf(ql[4*c],   kv.x, x);
                x = fmaf(ql[4*c+1], kv.y, x);
                x = fmaf(ql[4*c+2], kv.z, x);
                x = fmaf(ql[4*c+3], kv.w, x);
            }
            float kg = (float)(kt + kk);
            float bias = (sf - fabsf(qf - kg)) * invs;
            x = fmaf(x, scale, bias);
            if (x > m) {
                float corr = __expf(m - x);
                l *= corr;
                #pragma unroll
                for (int d = 0; d < NDH; d++) acc[d] *= corr;
                m = x;
            }
            float p = __expf(x - m);
            l += p;
            const float4* vr = (const float4*)(Vs + kk * NDH);
            #pragma unroll
            for (int c = 0; c < 8; c++) {
                float4 vv = vr[c];
                acc[4*c]   = fmaf(p, vv.x, acc[4*c]);
                acc[4*c+1] = fmaf(p, vv.y, acc[4*c+1]);
                acc[4*c+2] = fmaf(p, vv.z, acc[4*c+2]);
                acc[4*c+3] = fmaf(p, vv.w, acc[4*c+3]);
            }
        }
    }

    const float inv = 1.f / l;
    float* out = gCtx + ((size_t)(b * NL + q)) * ND + h * NDH;
    #pragma unroll
    for (int c = 0; c < 8; c++) {
        float4 o;
        o.x = acc[4*c]   * inv;
        o.y = acc[4*c+1] * inv;
        o.z = acc[4*c+2] * inv;
        o.w = acc[4*c+3] * inv;
        ((float4*)out)[c] = o;
    }
}

// ---------------- launcher ----------------
extern "C" void kernel_launch(void* const* d_in, const int* in_sizes, int n_in,
                              void* d_out, int out_size) {
    const float* src       = (const float*)d_in[0];
    const unsigned char* mask = (const unsigned char*)d_in[1];
    const float* in_proj_w = (const float*)d_in[2];
    const float* in_proj_b = (const float*)d_in[3];
    const float* out_w     = (const float*)d_in[4];
    const float* out_b     = (const float*)d_in[5];
    const float* proj_w    = (const float*)d_in[6];
    const float* proj_b    = (const float*)d_in[7];
    const float* ff1_w     = (const float*)d_in[8];
    const float* ff1_b     = (const float*)d_in[9];
    const float* ff2_w     = (const float*)d_in[10];
    const float* ff2_b     = (const float*)d_in[11];
    float* out = (float*)d_out;

    float *pCtx, *pH, *pFF, *pWc, *pBc;
    cudaGetSymbolAddress((void**)&pCtx, gCtx);
    cudaGetSymbolAddress((void**)&pH,   gH);
    cudaGetSymbolAddress((void**)&pFF,  gFF);
    cudaGetSymbolAddress((void**)&pWc,  gWc);
    cudaGetSymbolAddress((void**)&pBc,  gBc);

    detect_mask_kernel<<<1, 256>>>(mask);
    lengths_kernel<<<NB, 256>>>(mask);
    fuse_w_kernel<<<ND, ND>>>(proj_w, out_w);
    fuse_b_kernel<<<1, ND>>>(proj_w, out_b, proj_b);

    // QKV: [8192,256] @ [768,256]^T -> scatter to gQ/gK/gV
    {
        dim3 g(6, 64);
        sgemm_k<0><<<g, 256>>>(src, in_proj_w, in_proj_b, nullptr, nullptr, NM, 3*ND, ND);
    }
    // attention
    {
        dim3 g(8, NB * NH);
        attn_kernel<<<g, 128>>>();
    }
    // h = src + ctx @ Wc^T + bc
    {
        dim3 g(2, 64);
        sgemm_k<1><<<g, 256>>>(pCtx, pWc, pBc, src, pH, NM, ND, ND);
    }
    // g = gelu(h @ ff1_w^T + ff1_b)
    {
        dim3 g(16, 64);
        sgemm_k<2><<<g, 256>>>(pH, ff1_w, ff1_b, nullptr, pFF, NM, NDFF, ND);
    }
    // out = h + g @ ff2_w^T + ff2_b, padded rows zeroed
    {
        dim3 g(2, 64);
        sgemm_k<3><<<g, 256>>>(pFF, ff2_w, ff2_b, pH, out, NM, ND, NDFF);
    }
}

// round 3
// speedup vs baseline: 1.6033x; 1.6033x over previous
#include <cuda_runtime.h>
#include <cuda_bf16.h>
#include <math.h>
#include <stdint.h>

#define NB 8
#define NL 1024
#define ND 256
#define NH 8
#define NDH 32
#define NDFF 2048
#define NM (NB*NL)

// ---------------- scratch (device globals; allocation-free) ----------------
__device__ float gQ[NB*NH*NL*NDH];
__device__ float gK[NB*NH*NL*NDH];
__device__ float gV[NB*NH*NL*NDH];
__device__ float gH[NM*ND];
__device__ __nv_bfloat16 gSrcHi[NM*ND],  gSrcLo[NM*ND];
__device__ __nv_bfloat16 gCtxHi[NM*ND],  gCtxLo[NM*ND];
__device__ __nv_bfloat16 gHHi[NM*ND],    gHLo[NM*ND];
__device__ __nv_bfloat16 gFFHi[(size_t)NM*NDFF], gFFLo[(size_t)NM*NDFF];
__device__ __nv_bfloat16 gWqkvHi[3*ND*ND], gWqkvLo[3*ND*ND];
__device__ __nv_bfloat16 gWcHi[ND*ND],     gWcLo[ND*ND];
__device__ __nv_bfloat16 gW1Hi[NDFF*ND],   gW1Lo[NDFF*ND];
__device__ __nv_bfloat16 gW2Hi[ND*NDFF],   gW2Lo[ND*NDFF];
__device__ float gBc[ND];
__device__ int   gLen[NB];
__device__ int   gMode;

// ---------------- helpers ----------------
__device__ __forceinline__ uint32_t smem_u32(const void* p) {
    uint32_t a;
    asm("{ .reg .u64 t; cvta.to.shared.u64 t, %1; cvt.u32.u64 %0, t; }" : "=r"(a) : "l"(p));
    return a;
}
__device__ __forceinline__ void cpasync16(uint32_t saddr, const void* gaddr) {
    asm volatile("cp.async.cg.shared.global [%0], [%1], 16;" :: "r"(saddr), "l"(gaddr) : "memory");
}
#define CP_COMMIT() asm volatile("cp.async.commit_group;" ::: "memory")
#define CP_WAIT(n)  asm volatile("cp.async.wait_group %0;" :: "n"(n) : "memory")

#define LDSM_X4(r0, r1, r2, r3, addr) \
    asm volatile("ldmatrix.sync.aligned.m8n8.x4.shared.b16 {%0,%1,%2,%3}, [%4];" \
        : "=r"(r0), "=r"(r1), "=r"(r2), "=r"(r3) : "r"(addr))

#define MMA16816(d, a, b0, b1) \
    asm volatile("mma.sync.aligned.m16n8k16.row.col.f32.bf16.bf16.f32 " \
        "{%0,%1,%2,%3}, {%4,%5,%6,%7}, {%8,%9}, {%0,%1,%2,%3};" \
        : "+f"((d)[0]), "+f"((d)[1]), "+f"((d)[2]), "+f"((d)[3]) \
        : "r"((a)[0]), "r"((a)[1]), "r"((a)[2]), "r"((a)[3]), "r"(b0), "r"(b1))

__device__ __forceinline__ float gelu_f(float x) {
    return 0.5f * x * (1.f + erff(x * 0.7071067811865475f));
}
__device__ __forceinline__ uint32_t pack2_hi(float a, float b) {
    __nv_bfloat16 h0 = __float2bfloat16(a), h1 = __float2bfloat16(b);
    return ((uint32_t)__bfloat16_as_ushort(h1) << 16) | __bfloat16_as_ushort(h0);
}
__device__ __forceinline__ uint32_t pack2_lo(float a, float b) {
    __nv_bfloat16 h0 = __float2bfloat16(a), h1 = __float2bfloat16(b);
    float l0 = a - __bfloat162float(h0), l1 = b - __bfloat162float(h1);
    __nv_bfloat16 g0 = __float2bfloat16(l0), g1 = __float2bfloat16(l1);
    return ((uint32_t)__bfloat16_as_ushort(g1) << 16) | __bfloat16_as_ushort(g0);
}

// ---------------- mask dtype detection + lengths ----------------
__global__ void detect_mask_kernel(const unsigned char* __restrict__ mb) {
    __shared__ int flag;
    if (threadIdx.x == 0) flag = 0;
    __syncthreads();
    int f = 0;
    for (int i = threadIdx.x; i < NB*NL; i += blockDim.x)
        if ((i & 3) != 0 && mb[i] != 0) f = 1;
    if (f) atomicOr(&flag, 1);
    __syncthreads();
    if (threadIdx.x == 0) gMode = flag;
}
__global__ void lengths_kernel(const unsigned char* __restrict__ mb) {
    int b = blockIdx.x;
    __shared__ int cnt;
    if (threadIdx.x == 0) cnt = 0;
    __syncthreads();
    int mode = gMode, c = 0;
    for (int i = threadIdx.x; i < NL; i += blockDim.x) {
        int pad = mode ? (mb[b*NL + i] != 0) : (((const int*)mb)[b*NL + i] != 0);
        if (!pad) c++;
    }
    atomicAdd(&cnt, c);
    __syncthreads();
    if (threadIdx.x == 0) gLen[b] = cnt;
}

// ---------------- fp32 -> bf16 hi/lo conversion ----------------
__global__ void conv_kernel(const float* __restrict__ x, __nv_bfloat16* __restrict__ hi,
                            __nv_bfloat16* __restrict__ lo, int n4) {
    int i = blockIdx.x * 256 + threadIdx.x;
    if (i >= n4) return;
    float4 f = ((const float4*)x)[i];
    uint2 h, l;
    h.x = pack2_hi(f.x, f.y); h.y = pack2_hi(f.z, f.w);
    l.x = pack2_lo(f.x, f.y); l.y = pack2_lo(f.z, f.w);
    ((uint2*)hi)[i] = h;
    ((uint2*)lo)[i] = l;
}

// ---------------- weight fusion ----------------
__global__ void fuse_w_kernel(const float* __restrict__ pw, const float* __restrict__ ow) {
    int i = blockIdx.x, j = threadIdx.x;
    float s = 0.f;
    #pragma unroll 8
    for (int k = 0; k < ND; k++)
        s = fmaf(pw[i*ND + k], ow[k*ND + j], s);
    __nv_bfloat16 h = __float2bfloat16(s);
    gWcHi[i*ND + j] = h;
    gWcLo[i*ND + j] = __float2bfloat16(s - __bfloat162float(h));
}
__global__ void fuse_b_kernel(const float* __restrict__ pw, const float* __restrict__ ob,
                              const float* __restrict__ pb) {
    int i = blockIdx.x, t = threadIdx.x;
    __shared__ float red[256];
    red[t] = pw[i*ND + t] * ob[t];
    __syncthreads();
    for (int o = 128; o > 0; o >>= 1) {
        if (t < o) red[t] += red[t + o];
        __syncthreads();
    }
    if (t == 0) gBc[i] = red[0] + pb[i];
}

// ---------------- mma.sync split-bf16 GEMM: C[M,N] = A[M,K] @ B[N,K]^T ----------------
// 128x128x32 block tile, 8 warps (4 along M x 2 along N), warp tile 32x64.
// smem rows padded to 40 bf16 (80B stride) -> conflict-free ldmatrix.
// EPI 0: QKV scatter (+bias) -> gQ/gK/gV fp32
// EPI 1: Cf = acc+bias+res; also hi/lo
// EPI 2: gelu(acc+bias) -> hi/lo only
// EPI 3: Cf = acc+bias+res, padded rows zeroed
#define TILE_B 10240          // one matrix tile: 128 rows * 80 bytes
#define STAGE_B (4*TILE_B)    // Ahi, Alo, Bhi, Blo
#define SMEM_DYN (2*STAGE_B)  // double buffer = 81920

template<int EPI>
__global__ __launch_bounds__(256) void mma_gemm(
    const __nv_bfloat16* __restrict__ Ahi, const __nv_bfloat16* __restrict__ Alo,
    const __nv_bfloat16* __restrict__ Bhi, const __nv_bfloat16* __restrict__ Blo,
    const float* __restrict__ bias, const float* __restrict__ res,
    float* __restrict__ Cf, __nv_bfloat16* __restrict__ Chi, __nv_bfloat16* __restrict__ Clo,
    int M, int N, int K)
{
    extern __shared__ char sm[];
    const uint32_t sb = smem_u32(sm);
    const int tid = threadIdx.x;
    const int lane = tid & 31, wid = tid >> 5;
    const int wm = wid & 3, wn = wid >> 2;
    const int bm = blockIdx.y * 128, bn = blockIdx.x * 128;

    float acc[2][8][4];
    #pragma unroll
    for (int i = 0; i < 2; i++)
        #pragma unroll
        for (int j = 0; j < 8; j++)
            #pragma unroll
            for (int c = 0; c < 4; c++) acc[i][j][c] = 0.f;

    const int nt = K >> 5;

    auto prefetch = [&](int stage, int kt) {
        const int k0 = kt << 5;
        #pragma unroll
        for (int it = 0; it < 8; it++) {
            int u = (it << 8) + tid;
            int mat = u >> 9, w = u & 511, r = w >> 2, c = w & 3;
            const __nv_bfloat16* g;
            int rb;
            if      (mat == 0) { g = Ahi; rb = bm; }
            else if (mat == 1) { g = Alo; rb = bm; }
            else if (mat == 2) { g = Bhi; rb = bn; }
            else               { g = Blo; rb = bn; }
            const void* ga = g + (size_t)(rb + r) * K + k0 + (c << 3);
            uint32_t sa = sb + (uint32_t)(stage * STAGE_B + mat * TILE_B + r * 80 + (c << 4));
            cpasync16(sa, ga);
        }
        CP_COMMIT();
    };

    auto compute = [&](int stage) {
        const uint32_t stb = sb + (uint32_t)(stage * STAGE_B);
        #pragma unroll
        for (int ks = 0; ks < 2; ks++) {
            uint32_t af[2][2][4];
            #pragma unroll
            for (int d = 0; d < 2; d++)
                #pragma unroll
                for (int fm = 0; fm < 2; fm++) {
                    int row = wm * 32 + fm * 16 + (lane & 15);
                    int chunk = ks * 2 + (lane >> 4);
                    uint32_t a = stb + (uint32_t)(d * TILE_B + row * 80 + chunk * 16);
                    LDSM_X4(af[d][fm][0], af[d][fm][1], af[d][fm][2], af[d][fm][3], a);
                }
            uint32_t bh_[4][4], bl_[4][4];
            #pragma unroll
            for (int d = 0; d < 2; d++)
                #pragma unroll
                for (int fq = 0; fq < 4; fq++) {
                    int g = lane >> 3;
                    int row = wn * 64 + fq * 16 + ((g >> 1) << 3) + (lane & 7);
                    int chunk = ks * 2 + (g & 1);
                    uint32_t a = stb + (uint32_t)((2 + d) * TILE_B + row * 80 + chunk * 16);
                    uint32_t* dst = d ? bl_[fq] : bh_[fq];
                    LDSM_X4(dst[0], dst[1], dst[2], dst[3], a);
                }
            #pragma unroll
            for (int fm = 0; fm < 2; fm++)
                #pragma unroll
                for (int fn = 0; fn < 8; fn++) {
                    uint32_t bh0 = bh_[fn >> 1][(fn & 1) * 2], bh1 = bh_[fn >> 1][(fn & 1) * 2 + 1];
                    uint32_t bl0 = bl_[fn >> 1][(fn & 1) * 2], bl1 = bl_[fn >> 1][(fn & 1) * 2 + 1];
                    MMA16816(acc[fm][fn], af[0][fm], bh0, bh1);
                    MMA16816(acc[fm][fn], af[0][fm], bl0, bl1);
                    MMA16816(acc[fm][fn], af[1][fm], bh0, bh1);
                }
        }
    };

    prefetch(0, 0);
    for (int i = 0; i < nt; i++) {
        if (i + 1 < nt) {
            prefetch((i + 1) & 1, i + 1);
            CP_WAIT(1);
        } else {
            CP_WAIT(0);
        }
        __syncthreads();
        compute(i & 1);
        __syncthreads();
    }

    // ---------------- epilogue (m16n8 fragment layout) ----------------
    const int tq = lane >> 2, tr2 = (lane & 3) << 1;
    #pragma unroll
    for (int fm = 0; fm < 2; fm++) {
        #pragma unroll
        for (int fn = 0; fn < 8; fn++) {
            int col = bn + wn * 64 + fn * 8 + tr2;
            float b0 = __ldg(bias + col), b1 = __ldg(bias + col + 1);
            #pragma unroll
            for (int half = 0; half < 2; half++) {
                int row = bm + wm * 32 + fm * 16 + tq + half * 8;
                float v0 = acc[fm][fn][half * 2]     + b0;
                float v1 = acc[fm][fn][half * 2 + 1] + b1;
                if (EPI == 0) {
                    int t = col >> 8, h = (col & 255) >> 5, dh = col & 31;
                    int bb = row >> 10, ll = row & 1023;
                    float* dst = (t == 0) ? gQ : (t == 1) ? gK : gV;
                    float2* p = (float2*)(dst + (((size_t)(bb * NH + h)) * NL + ll) * NDH + dh);
                    *p = make_float2(v0, v1);
                } else if (EPI == 1) {
                    size_t o = (size_t)row * N + col;
                    v0 += __ldg(res + o); v1 += __ldg(res + o + 1);
                    *(float2*)(Cf + o) = make_float2(v0, v1);
                    *(uint32_t*)(Chi + o) = pack2_hi(v0, v1);
                    *(uint32_t*)(Clo + o) = pack2_lo(v0, v1);
                } else if (EPI == 2) {
                    size_t o = (size_t)row * N + col;
                    v0 = gelu_f(v0); v1 = gelu_f(v1);
                    *(uint32_t*)(Chi + o) = pack2_hi(v0, v1);
                    *(uint32_t*)(Clo + o) = pack2_lo(v0, v1);
                } else {
                    size_t o = (size_t)row * N + col;
                    v0 += __ldg(res + o); v1 += __ldg(res + o + 1);
                    int bb = row >> 10, ll = row & 1023;
                    if (ll >= gLen[bb]) { v0 = 0.f; v1 = 0.f; }
                    *(float2*)(Cf + o) = make_float2(v0, v1);
                }
            }
        }
    }
}

// ---------------- flash attention (fp32, DH=32) -> ctx hi/lo ----------------
__global__ __launch_bounds__(128) void attn_kernel() {
    const int tid = threadIdx.x;
    const int bh = blockIdx.y;
    const int b = bh >> 3, h = bh & 7;
    const int q = blockIdx.x * 128 + tid;

    const float* Qp = gQ + (size_t)bh * NL * NDH + (size_t)q * NDH;
    const float* Kp = gK + (size_t)bh * NL * NDH;
    const float* Vp = gV + (size_t)bh * NL * NDH;

    __shared__ float Ks[64 * NDH];
    __shared__ float Vs[64 * NDH];

    float ql[NDH];
    #pragma unroll
    for (int d = 0; d < NDH; d++) ql[d] = Qp[d];

    const int S = gLen[b];
    const float sf = (float)S;
    const float invs = 1.f / sf;
    const float scale = 0.1767766952966369f;
    const float qf = (float)q;

    float m = -1e30f, l = 0.f;
    float acc[NDH];
    #pragma unroll
    for (int d = 0; d < NDH; d++) acc[d] = 0.f;

    for (int kt = 0; kt < S; kt += 64) {
        __syncthreads();
        const float4* Kg = (const float4*)(Kp + (size_t)kt * NDH);
        const float4* Vg = (const float4*)(Vp + (size_t)kt * NDH);
        #pragma unroll
        for (int i = 0; i < 4; i++) {
            ((float4*)Ks)[tid + i * 128] = Kg[tid + i * 128];
            ((float4*)Vs)[tid + i * 128] = Vg[tid + i * 128];
        }
        __syncthreads();
        const int kmax = min(64, S - kt);
        for (int kk = 0; kk < kmax; kk++) {
            const float4* kr = (const float4*)(Ks + kk * NDH);
            float x = 0.f;
            #pragma unroll
            for (int c = 0; c < 8; c++) {
                float4 kv = kr[c];
                x = fmaf(ql[4*c],   kv.x, x);
                x = fmaf(ql[4*c+1], kv.y, x);
                x = fmaf(ql[4*c+2], kv.z, x);
                x = fmaf(ql[4*c+3], kv.w, x);
            }
            float kg = (float)(kt + kk);
            float bias = (sf - fabsf(qf - kg)) * invs;
            x = fmaf(x, scale, bias);
            if (x > m) {
                float corr = __expf(m - x);
                l *= corr;
                #pragma unroll
                for (int d = 0; d < NDH; d++) acc[d] *= corr;
                m = x;
            }
            float p = __expf(x - m);
            l += p;
            const float4* vr = (const float4*)(Vs + kk * NDH);
            #pragma unroll
            for (int c = 0; c < 8; c++) {
                float4 vv = vr[c];
                acc[4*c]   = fmaf(p, vv.x, acc[4*c]);
                acc[4*c+1] = fmaf(p, vv.y, acc[4*c+1]);
                acc[4*c+2] = fmaf(p, vv.z, acc[4*c+2]);
                acc[4*c+3] = fmaf(p, vv.w, acc[4*c+3]);
            }
        }
    }

    const float inv = 1.f / l;
    float o[NDH];
    #pragma unroll
    for (int d = 0; d < NDH; d++) o[d] = acc[d] * inv;

    size_t base = ((size_t)(b * NL + q)) * ND + h * NDH;
    uint32_t hp[16], lp[16];
    #pragma unroll
    for (int j = 0; j < 16; j++) {
        hp[j] = pack2_hi(o[2*j], o[2*j+1]);
        lp[j] = pack2_lo(o[2*j], o[2*j+1]);
    }
    #pragma unroll
    for (int qd = 0; qd < 4; qd++) {
        ((uint4*)(gCtxHi + base))[qd] = make_uint4(hp[4*qd], hp[4*qd+1], hp[4*qd+2], hp[4*qd+3]);
        ((uint4*)(gCtxLo + base))[qd] = make_uint4(lp[4*qd], lp[4*qd+1], lp[4*qd+2], lp[4*qd+3]);
    }
}

// ---------------- launcher ----------------
extern "C" void kernel_launch(void* const* d_in, const int* in_sizes, int n_in,
                              void* d_out, int out_size) {
    const float* src       = (const float*)d_in[0];
    const unsigned char* mask = (const unsigned char*)d_in[1];
    const float* in_proj_w = (const float*)d_in[2];
    const float* in_proj_b = (const float*)d_in[3];
    const float* out_w     = (const float*)d_in[4];
    const float* out_b     = (const float*)d_in[5];
    const float* proj_w    = (const float*)d_in[6];
    const float* proj_b    = (const float*)d_in[7];
    const float* ff1_w     = (const float*)d_in[8];
    const float* ff1_b     = (const float*)d_in[9];
    const float* ff2_w     = (const float*)d_in[10];
    const float* ff2_b     = (const float*)d_in[11];
    float* out = (float*)d_out;

    cudaFuncSetAttribute(mma_gemm<0>, cudaFuncAttributeMaxDynamicSharedMemorySize, SMEM_DYN);
    cudaFuncSetAttribute(mma_gemm<1>, cudaFuncAttributeMaxDynamicSharedMemorySize, SMEM_DYN);
    cudaFuncSetAttribute(mma_gemm<2>, cudaFuncAttributeMaxDynamicSharedMemorySize, SMEM_DYN);
    cudaFuncSetAttribute(mma_gemm<3>, cudaFuncAttributeMaxDynamicSharedMemorySize, SMEM_DYN);

    float *pH, *pBc;
    __nv_bfloat16 *pSrcHi, *pSrcLo, *pCtxHi, *pCtxLo, *pHHi, *pHLo, *pFFHi, *pFFLo;
    __nv_bfloat16 *pWqkvHi, *pWqkvLo, *pWcHi, *pWcLo, *pW1Hi, *pW1Lo, *pW2Hi, *pW2Lo;
    cudaGetSymbolAddress((void**)&pH, gH);
    cudaGetSymbolAddress((void**)&pBc, gBc);
    cudaGetSymbolAddress((void**)&pSrcHi, gSrcHi);  cudaGetSymbolAddress((void**)&pSrcLo, gSrcLo);
    cudaGetSymbolAddress((void**)&pCtxHi, gCtxHi);  cudaGetSymbolAddress((void**)&pCtxLo, gCtxLo);
    cudaGetSymbolAddress((void**)&pHHi, gHHi);      cudaGetSymbolAddress((void**)&pHLo, gHLo);
    cudaGetSymbolAddress((void**)&pFFHi, gFFHi);    cudaGetSymbolAddress((void**)&pFFLo, gFFLo);
    cudaGetSymbolAddress((void**)&pWqkvHi, gWqkvHi); cudaGetSymbolAddress((void**)&pWqkvLo, gWqkvLo);
    cudaGetSymbolAddress((void**)&pWcHi, gWcHi);    cudaGetSymbolAddress((void**)&pWcLo, gWcLo);
    cudaGetSymbolAddress((void**)&pW1Hi, gW1Hi);    cudaGetSymbolAddress((void**)&pW1Lo, gW1Lo);
    cudaGetSymbolAddress((void**)&pW2Hi, gW2Hi);    cudaGetSymbolAddress((void**)&pW2Lo, gW2Lo);

    // setup
    detect_mask_kernel<<<1, 256>>>(mask);
    lengths_kernel<<<NB, 256>>>(mask);
    conv_kernel<<<(NM*ND/4 + 255)/256, 256>>>(src, pSrcHi, pSrcLo, NM*ND/4);
    conv_kernel<<<(3*ND*ND/4 + 255)/256, 256>>>(in_proj_w, pWqkvHi, pWqkvLo, 3*ND*ND/4);
    conv_kernel<<<(NDFF*ND/4 + 255)/256, 256>>>(ff1_w, pW1Hi, pW1Lo, NDFF*ND/4);
    conv_kernel<<<(ND*NDFF/4 + 255)/256, 256>>>(ff2_w, pW2Hi, pW2Lo, ND*NDFF/4);
    fuse_w_kernel<<<ND, ND>>>(proj_w, out_w);
    fuse_b_kernel<<<ND, 256>>>(proj_w, out_b, proj_b);

    // QKV = src @ in_proj_w^T + b -> scatter Q/K/V
    mma_gemm<0><<<dim3(6, 64), 256, SMEM_DYN>>>(pSrcHi, pSrcLo, pWqkvHi, pWqkvLo,
        in_proj_b, nullptr, nullptr, nullptr, nullptr, NM, 3*ND, ND);
    // attention -> ctx hi/lo
    attn_kernel<<<dim3(8, NB*NH), 128>>>();
    // h = src + ctx @ Wc^T + bc  (fp32 + hi/lo)
    mma_gemm<1><<<dim3(2, 64), 256, SMEM_DYN>>>(pCtxHi, pCtxLo, pWcHi, pWcLo,
        pBc, src, pH, pHHi, pHLo, NM, ND, ND);
    // ff = gelu(h @ ff1_w^T + b1) -> hi/lo
    mma_gemm<2><<<dim3(16, 64), 256, SMEM_DYN>>>(pHHi, pHLo, pW1Hi, pW1Lo,
        ff1_b, nullptr, nullptr, pFFHi, pFFLo, NM, NDFF, ND);
    // out = h + ff @ ff2_w^T + b2, padded rows zeroed
    mma_gemm<3><<<dim3(2, 64), 256, SMEM_DYN>>>(pFFHi, pFFLo, pW2Hi, pW2Lo,
        ff2_b, pH, out, nullptr, nullptr, NM, ND, NDFF);
}

// round 4
// speedup vs baseline: 2.5976x; 1.6202x over previous
#include <cuda_runtime.h>
#include <cuda_bf16.h>
#include <math.h>
#include <stdint.h>

#define NB 8
#define NL 1024
#define ND 256
#define NH 8
#define NDH 32
#define NDFF 2048
#define NM (NB*NL)

// ---------------- scratch (device globals; allocation-free) ----------------
__device__ float gH[NM*ND];
__device__ __nv_bfloat16 gQhi[64*NL*NDH], gQlo[64*NL*NDH];
__device__ __nv_bfloat16 gKhi[64*NL*NDH], gKlo[64*NL*NDH];
__device__ __nv_bfloat16 gVhi[64*NL*NDH];
__device__ __nv_bfloat16 gSrcHi[NM*ND],  gSrcLo[NM*ND];
__device__ __nv_bfloat16 gCtxHi[NM*ND],  gCtxLo[NM*ND];
__device__ __nv_bfloat16 gHHi[NM*ND],    gHLo[NM*ND];
__device__ __nv_bfloat16 gFFHi[(size_t)NM*NDFF], gFFLo[(size_t)NM*NDFF];
__device__ __nv_bfloat16 gWqkvHi[3*ND*ND], gWqkvLo[3*ND*ND];
__device__ __nv_bfloat16 gWcHi[ND*ND],     gWcLo[ND*ND];
__device__ __nv_bfloat16 gW1Hi[NDFF*ND],   gW1Lo[NDFF*ND];
__device__ __nv_bfloat16 gW2Hi[ND*NDFF],   gW2Lo[ND*NDFF];
__device__ float gBc[ND];
__device__ int   gLen[NB];
__device__ int   gMode;

// ---------------- helpers ----------------
__device__ __forceinline__ uint32_t smem_u32(const void* p) {
    uint32_t a;
    asm("{ .reg .u64 t; cvta.to.shared.u64 t, %1; cvt.u32.u64 %0, t; }" : "=r"(a) : "l"(p));
    return a;
}
__device__ __forceinline__ void cpasync16(uint32_t saddr, const void* gaddr) {
    asm volatile("cp.async.cg.shared.global [%0], [%1], 16;" :: "r"(saddr), "l"(gaddr) : "memory");
}
#define CP_COMMIT() asm volatile("cp.async.commit_group;" ::: "memory")
#define CP_WAIT(n)  asm volatile("cp.async.wait_group %0;" :: "n"(n) : "memory")

#define LDSM_X4(r0, r1, r2, r3, addr) \
    asm volatile("ldmatrix.sync.aligned.m8n8.x4.shared.b16 {%0,%1,%2,%3}, [%4];" \
        : "=r"(r0), "=r"(r1), "=r"(r2), "=r"(r3) : "r"(addr))
#define LDSM_X4_T(r0, r1, r2, r3, addr) \
    asm volatile("ldmatrix.sync.aligned.m8n8.x4.trans.shared.b16 {%0,%1,%2,%3}, [%4];" \
        : "=r"(r0), "=r"(r1), "=r"(r2), "=r"(r3) : "r"(addr))

#define MMA16816(d, a, b0, b1) \
    asm volatile("mma.sync.aligned.m16n8k16.row.col.f32.bf16.bf16.f32 " \
        "{%0,%1,%2,%3}, {%4,%5,%6,%7}, {%8,%9}, {%0,%1,%2,%3};" \
        : "+f"((d)[0]), "+f"((d)[1]), "+f"((d)[2]), "+f"((d)[3]) \
        : "r"((a)[0]), "r"((a)[1]), "r"((a)[2]), "r"((a)[3]), "r"(b0), "r"(b1))

__device__ __forceinline__ float gelu_f(float x) {
    return 0.5f * x * (1.f + erff(x * 0.7071067811865475f));
}
__device__ __forceinline__ uint32_t pack2_hi(float a, float b) {
    __nv_bfloat16 h0 = __float2bfloat16(a), h1 = __float2bfloat16(b);
    return ((uint32_t)__bfloat16_as_ushort(h1) << 16) | __bfloat16_as_ushort(h0);
}
__device__ __forceinline__ uint32_t pack2_lo(float a, float b) {
    __nv_bfloat16 h0 = __float2bfloat16(a), h1 = __float2bfloat16(b);
    float l0 = a - __bfloat162float(h0), l1 = b - __bfloat162float(h1);
    __nv_bfloat16 g0 = __float2bfloat16(l0), g1 = __float2bfloat16(l1);
    return ((uint32_t)__bfloat16_as_ushort(g1) << 16) | __bfloat16_as_ushort(g0);
}

// ---------------- mask dtype detection + lengths ----------------
__global__ void detect_mask_kernel(const unsigned char* __restrict__ mb) {
    __shared__ int flag;
    if (threadIdx.x == 0) flag = 0;
    __syncthreads();
    int f = 0;
    for (int i = threadIdx.x; i < NB*NL; i += blockDim.x)
        if ((i & 3) != 0 && mb[i] != 0) f = 1;
    if (f) atomicOr(&flag, 1);
    __syncthreads();
    if (threadIdx.x == 0) gMode = flag;
}
__global__ void lengths_kernel(const unsigned char* __restrict__ mb) {
    int b = blockIdx.x;
    __shared__ int cnt;
    if (threadIdx.x == 0) cnt = 0;
    __syncthreads();
    int mode = gMode, c = 0;
    for (int i = threadIdx.x; i < NL; i += blockDim.x) {
        int pad = mode ? (mb[b*NL + i] != 0) : (((const int*)mb)[b*NL + i] != 0);
        if (!pad) c++;
    }
    atomicAdd(&cnt, c);
    __syncthreads();
    if (threadIdx.x == 0) gLen[b] = cnt;
}

// ---------------- fp32 -> bf16 hi/lo conversion ----------------
__global__ void conv_kernel(const float* __restrict__ x, __nv_bfloat16* __restrict__ hi,
                            __nv_bfloat16* __restrict__ lo, int n4) {
    int i = blockIdx.x * 256 + threadIdx.x;
    if (i >= n4) return;
    float4 f = ((const float4*)x)[i];
    uint2 h, l;
    h.x = pack2_hi(f.x, f.y); h.y = pack2_hi(f.z, f.w);
    l.x = pack2_lo(f.x, f.y); l.y = pack2_lo(f.z, f.w);
    ((uint2*)hi)[i] = h;
    ((uint2*)lo)[i] = l;
}

// ---------------- weight fusion ----------------
__global__ void fuse_w_kernel(const float* __restrict__ pw, const float* __restrict__ ow) {
    int i = blockIdx.x, j = threadIdx.x;
    float s = 0.f;
    #pragma unroll 8
    for (int k = 0; k < ND; k++)
        s = fmaf(pw[i*ND + k], ow[k*ND + j], s);
    __nv_bfloat16 h = __float2bfloat16(s);
    gWcHi[i*ND + j] = h;
    gWcLo[i*ND + j] = __float2bfloat16(s - __bfloat162float(h));
}
__global__ void fuse_b_kernel(const float* __restrict__ pw, const float* __restrict__ ob,
                              const float* __restrict__ pb) {
    int i = blockIdx.x, t = threadIdx.x;
    __shared__ float red[256];
    red[t] = pw[i*ND + t] * ob[t];
    __syncthreads();
    for (int o = 128; o > 0; o >>= 1) {
        if (t < o) red[t] += red[t + o];
        __syncthreads();
    }
    if (t == 0) gBc[i] = red[0] + pb[i];
}

// ---------------- mma.sync split-bf16 GEMM: C[M,N] = A[M,K] @ B[N,K]^T ----------------
#define TILE_B 10240
#define STAGE_B (4*TILE_B)
#define SMEM_DYN (2*STAGE_B)

template<int EPI>
__global__ __launch_bounds__(256) void mma_gemm(
    const __nv_bfloat16* __restrict__ Ahi, const __nv_bfloat16* __restrict__ Alo,
    const __nv_bfloat16* __restrict__ Bhi, const __nv_bfloat16* __restrict__ Blo,
    const float* __restrict__ bias, const float* __restrict__ res,
    float* __restrict__ Cf, __nv_bfloat16* __restrict__ Chi, __nv_bfloat16* __restrict__ Clo,
    int M, int N, int K)
{
    extern __shared__ char sm[];
    const uint32_t sb = smem_u32(sm);
    const int tid = threadIdx.x;
    const int lane = tid & 31, wid = tid >> 5;
    const int wm = wid & 3, wn = wid >> 2;
    const int bm = blockIdx.y * 128, bn = blockIdx.x * 128;

    float acc[2][8][4];
    #pragma unroll
    for (int i = 0; i < 2; i++)
        #pragma unroll
        for (int j = 0; j < 8; j++)
            #pragma unroll
            for (int c = 0; c < 4; c++) acc[i][j][c] = 0.f;

    const int nt = K >> 5;

    auto prefetch = [&](int stage, int kt) {
        const int k0 = kt << 5;
        #pragma unroll
        for (int it = 0; it < 8; it++) {
            int u = (it << 8) + tid;
            int mat = u >> 9, w = u & 511, r = w >> 2, c = w & 3;
            const __nv_bfloat16* g;
            int rb;
            if      (mat == 0) { g = Ahi; rb = bm; }
            else if (mat == 1) { g = Alo; rb = bm; }
            else if (mat == 2) { g = Bhi; rb = bn; }
            else               { g = Blo; rb = bn; }
            const void* ga = g + (size_t)(rb + r) * K + k0 + (c << 3);
            uint32_t sa = sb + (uint32_t)(stage * STAGE_B + mat * TILE_B + r * 80 + (c << 4));
            cpasync16(sa, ga);
        }
        CP_COMMIT();
    };

    auto compute = [&](int stage) {
        const uint32_t stb = sb + (uint32_t)(stage * STAGE_B);
        #pragma unroll
        for (int ks = 0; ks < 2; ks++) {
            uint32_t af[2][2][4];
            #pragma unroll
            for (int d = 0; d < 2; d++)
                #pragma unroll
                for (int fm = 0; fm < 2; fm++) {
                    int row = wm * 32 + fm * 16 + (lane & 15);
                    int chunk = ks * 2 + (lane >> 4);
                    uint32_t a = stb + (uint32_t)(d * TILE_B + row * 80 + chunk * 16);
                    LDSM_X4(af[d][fm][0], af[d][fm][1], af[d][fm][2], af[d][fm][3], a);
                }
            uint32_t bh_[4][4], bl_[4][4];
            #pragma unroll
            for (int d = 0; d < 2; d++)
                #pragma unroll
                for (int fq = 0; fq < 4; fq++) {
                    int g = lane >> 3;
                    int row = wn * 64 + fq * 16 + ((g >> 1) << 3) + (lane & 7);
                    int chunk = ks * 2 + (g & 1);
                    uint32_t a = stb + (uint32_t)((2 + d) * TILE_B + row * 80 + chunk * 16);
                    uint32_t* dst = d ? bl_[fq] : bh_[fq];
                    LDSM_X4(dst[0], dst[1], dst[2], dst[3], a);
                }
            #pragma unroll
            for (int fm = 0; fm < 2; fm++)
                #pragma unroll
                for (int fn = 0; fn < 8; fn++) {
                    uint32_t bh0 = bh_[fn >> 1][(fn & 1) * 2], bh1 = bh_[fn >> 1][(fn & 1) * 2 + 1];
                    uint32_t bl0 = bl_[fn >> 1][(fn & 1) * 2], bl1 = bl_[fn >> 1][(fn & 1) * 2 + 1];
                    MMA16816(acc[fm][fn], af[0][fm], bh0, bh1);
                    MMA16816(acc[fm][fn], af[0][fm], bl0, bl1);
                    MMA16816(acc[fm][fn], af[1][fm], bh0, bh1);
                }
        }
    };

    prefetch(0, 0);
    for (int i = 0; i < nt; i++) {
        if (i + 1 < nt) {
            prefetch((i + 1) & 1, i + 1);
            CP_WAIT(1);
        } else {
            CP_WAIT(0);
        }
        __syncthreads();
        compute(i & 1);
        __syncthreads();
    }

    // ---------------- epilogue ----------------
    const int tq = lane >> 2, tr2 = (lane & 3) << 1;
    #pragma unroll
    for (int fm = 0; fm < 2; fm++) {
        #pragma unroll
        for (int fn = 0; fn < 8; fn++) {
            int col = bn + wn * 64 + fn * 8 + tr2;
            float b0 = __ldg(bias + col), b1 = __ldg(bias + col + 1);
            #pragma unroll
            for (int half = 0; half < 2; half++) {
                int row = bm + wm * 32 + fm * 16 + tq + half * 8;
                float v0 = acc[fm][fn][half * 2]     + b0;
                float v1 = acc[fm][fn][half * 2 + 1] + b1;
                if (EPI == 0) {
                    int t = col >> 8, h = (col & 255) >> 5, dh = col & 31;
                    int bb = row >> 10, ll = row & 1023;
                    size_t o = (((size_t)(bb * NH + h)) * NL + ll) * NDH + dh;
                    uint32_t hv = pack2_hi(v0, v1), lv = pack2_lo(v0, v1);
                    if (t == 0)      { *(uint32_t*)(gQhi + o) = hv; *(uint32_t*)(gQlo + o) = lv; }
                    else if (t == 1) { *(uint32_t*)(gKhi + o) = hv; *(uint32_t*)(gKlo + o) = lv; }
                    else             { *(uint32_t*)(gVhi + o) = hv; }
                } else if (EPI == 1) {
                    size_t o = (size_t)row * N + col;
                    v0 += __ldg(res + o); v1 += __ldg(res + o + 1);
                    *(float2*)(Cf + o) = make_float2(v0, v1);
                    *(uint32_t*)(Chi + o) = pack2_hi(v0, v1);
                    *(uint32_t*)(Clo + o) = pack2_lo(v0, v1);
                } else if (EPI == 2) {
                    size_t o = (size_t)row * N + col;
                    v0 = gelu_f(v0); v1 = gelu_f(v1);
                    *(uint32_t*)(Chi + o) = pack2_hi(v0, v1);
                    *(uint32_t*)(Clo + o) = pack2_lo(v0, v1);
                } else {
                    size_t o = (size_t)row * N + col;
                    v0 += __ldg(res + o); v1 += __ldg(res + o + 1);
                    int bb = row >> 10, ll = row & 1023;
                    if (ll >= gLen[bb]) { v0 = 0.f; v1 = 0.f; }
                    *(float2*)(Cf + o) = make_float2(v0, v1);
                }
            }
        }
    }
}

// ---------------- tensor-core flash attention ----------------
// Block: 64 q rows of one (b,h). 4 warps, each warp 16 q rows, all 64 keys/tile.
// smem rows padded to 80B. Q hi/lo resident; K hi/lo + V hi double-buffered.
#define AQ_B 5120            // one 64x32 bf16 tile w/ 80B stride
#define AKV_B (3*AQ_B)       // Khi, Klo, Vhi per stage

__global__ __launch_bounds__(128) void attn_mma_kernel() {
    __shared__ __align__(16) unsigned char smem[2*AQ_B + 2*AKV_B];
    const uint32_t sb = smem_u32(smem);
    const uint32_t sQhi = sb, sQlo = sb + AQ_B;
    const uint32_t sKV0 = sb + 2*AQ_B;

    const int tid = threadIdx.x, lane = tid & 31, wq = tid >> 5;
    const int bh = blockIdx.y, b = bh >> 3, h = bh & 7;
    const int qbase = blockIdx.x * 64;
    const int g = lane >> 3;
    const int tq = lane >> 2, tt = lane & 3;

    const __nv_bfloat16* Qh = gQhi + (size_t)bh * NL * NDH;
    const __nv_bfloat16* Ql = gQlo + (size_t)bh * NL * NDH;
    const __nv_bfloat16* Kh = gKhi + (size_t)bh * NL * NDH;
    const __nv_bfloat16* Kl = gKlo + (size_t)bh * NL * NDH;
    const __nv_bfloat16* Vh = gVhi + (size_t)bh * NL * NDH;

    const int S = gLen[b];
    const float sf = (float)S, invs = 1.f / sf;
    const float scale = 0.1767766952966369f;  // 1/sqrt(32)
    const int nt = (S + 63) >> 6;

    // --- stage Q (hi+lo) + first K/V tile ---
    #pragma unroll
    for (int it = 0; it < 4; it++) {
        int u = (it << 7) + tid;
        int mat = u >> 8, w = u & 255, r = w >> 2, c = w & 3;
        const __nv_bfloat16* gp = mat ? Ql : Qh;
        cpasync16((mat ? sQlo : sQhi) + (uint32_t)(r * 80 + (c << 4)),
                  gp + (size_t)(qbase + r) * NDH + (c << 3));
    }
    auto loadKV = [&](int stage, int kt) {
        uint32_t base = sKV0 + (uint32_t)stage * AKV_B;
        #pragma unroll
        for (int it = 0; it < 6; it++) {
            int u = (it << 7) + tid;
            int mat = u >> 8, w = u & 255, r = w >> 2, c = w & 3;
            const __nv_bfloat16* gp = (mat == 0) ? Kh : (mat == 1) ? Kl : Vh;
            cpasync16(base + (uint32_t)(mat * AQ_B + r * 80 + (c << 4)),
                      gp + (size_t)(kt + r) * NDH + (c << 3));
        }
        CP_COMMIT();
    };
    loadKV(0, 0);  // group includes Q chunks too

    uint32_t aQh[2][4], aQl[2][4];
    float oAcc[4][4];
    #pragma unroll
    for (int i = 0; i < 4; i++)
        #pragma unroll
        for (int j = 0; j < 4; j++) oAcc[i][j] = 0.f;
    float mrow0 = -1e30f, mrow1 = -1e30f, lp0 = 0.f, lp1 = 0.f;

    const float qr0 = (float)(qbase + wq * 16 + tq);
    const float qr1 = qr0 + 8.f;

    for (int i = 0; i < nt; i++) {
        if (i + 1 < nt) { loadKV((i + 1) & 1, (i + 1) << 6); CP_WAIT(1); }
        else            { CP_WAIT(0); }
        __syncthreads();

        if (i == 0) {
            #pragma unroll
            for (int ks = 0; ks < 2; ks++) {
                uint32_t roff = (uint32_t)((wq * 16 + ((g & 1) << 3) + (lane & 7)) * 80
                                           + 32 * ks + 16 * (g >> 1));
                LDSM_X4(aQh[ks][0], aQh[ks][1], aQh[ks][2], aQh[ks][3], sQhi + roff);
                LDSM_X4(aQl[ks][0], aQl[ks][1], aQl[ks][2], aQl[ks][3], sQlo + roff);
            }
        }

        const uint32_t sK  = sKV0 + (uint32_t)(i & 1) * AKV_B;
        const uint32_t sKl = sK + AQ_B;
        const uint32_t sV  = sK + 2 * AQ_B;
        const int kt = i << 6;

        // ---- S = scale*(QK^T) + bias ----
        float sA[8][4];
        #pragma unroll
        for (int j = 0; j < 8; j++)
            #pragma unroll
            for (int c = 0; c < 4; c++) sA[j][c] = 0.f;

        #pragma unroll
        for (int ks = 0; ks < 2; ks++) {
            #pragma unroll
            for (int jp = 0; jp < 4; jp++) {
                uint32_t kh[4], kl[4];
                uint32_t roff = (uint32_t)((16 * jp + ((g >> 1) << 3) + (lane & 7)) * 80
                                           + 32 * ks + 16 * (g & 1));
                LDSM_X4(kh[0], kh[1], kh[2], kh[3], sK + roff);
                LDSM_X4(kl[0], kl[1], kl[2], kl[3], sKl + roff);
                MMA16816(sA[2*jp],     aQh[ks], kh[0], kh[1]);
                MMA16816(sA[2*jp],     aQl[ks], kh[0], kh[1]);
                MMA16816(sA[2*jp],     aQh[ks], kl[0], kl[1]);
                MMA16816(sA[2*jp + 1], aQh[ks], kh[2], kh[3]);
                MMA16816(sA[2*jp + 1], aQl[ks], kh[2], kh[3]);
                MMA16816(sA[2*jp + 1], aQh[ks], kl[2], kl[3]);
            }
        }

        // ---- bias + online softmax ----
        float x[8][4];
        float tmax0 = -1e30f, tmax1 = -1e30f;
        #pragma unroll
        for (int j = 0; j < 8; j++) {
            int kc = kt + 8 * j + 2 * tt;
            float k0f = (float)kc, k1f = k0f + 1.f;
            float b00 = (kc     < S) ? (sf - fabsf(qr0 - k0f)) * invs : -1e30f;
            float b01 = (kc + 1 < S) ? (sf - fabsf(qr0 - k1f)) * invs : -1e30f;
            float b10 = (kc     < S) ? (sf - fabsf(qr1 - k0f)) * invs : -1e30f;
            float b11 = (kc + 1 < S) ? (sf - fabsf(qr1 - k1f)) * invs : -1e30f;
            x[j][0] = fmaf(sA[j][0], scale, b00);
            x[j][1] = fmaf(sA[j][1], scale, b01);
            x[j][2] = fmaf(sA[j][2], scale, b10);
            x[j][3] = fmaf(sA[j][3], scale, b11);
            tmax0 = fmaxf(tmax0, fmaxf(x[j][0], x[j][1]));
            tmax1 = fmaxf(tmax1, fmaxf(x[j][2], x[j][3]));
        }
        tmax0 = fmaxf(tmax0, __shfl_xor_sync(0xffffffff, tmax0, 1));
        tmax0 = fmaxf(tmax0, __shfl_xor_sync(0xffffffff, tmax0, 2));
        tmax1 = fmaxf(tmax1, __shfl_xor_sync(0xffffffff, tmax1, 1));
        tmax1 = fmaxf(tmax1, __shfl_xor_sync(0xffffffff, tmax1, 2));
        float mn0 = fmaxf(mrow0, tmax0), mn1 = fmaxf(mrow1, tmax1);
        float corr0 = __expf(mrow0 - mn0), corr1 = __expf(mrow1 - mn1);
        mrow0 = mn0; mrow1 = mn1;
        lp0 *= corr0; lp1 *= corr1;
        #pragma unroll
        for (int nf = 0; nf < 4; nf++) {
            oAcc[nf][0] *= corr0; oAcc[nf][1] *= corr0;
            oAcc[nf][2] *= corr1; oAcc[nf][3] *= corr1;
        }

        uint32_t aP[4][4];
        #pragma unroll
        for (int j = 0; j < 8; j++) {
            float p0 = __expf(x[j][0] - mn0), p1 = __expf(x[j][1] - mn0);
            float p2 = __expf(x[j][2] - mn1), p3 = __expf(x[j][3] - mn1);
            lp0 += p0 + p1; lp1 += p2 + p3;
            int jp = j >> 1, s2 = (j & 1) << 1;
            aP[jp][s2]     = pack2_hi(p0, p1);
            aP[jp][s2 + 1] = pack2_hi(p2, p3);
        }

        // ---- O += P @ V ----
        #pragma unroll
        for (int jp = 0; jp < 4; jp++) {
            uint32_t bv[8];
            uint32_t roff = (uint32_t)((16 * jp + ((g & 1) << 3) + (lane & 7)) * 80
                                       + 16 * (g >> 1));
            LDSM_X4_T(bv[0], bv[1], bv[2], bv[3], sV + roff);
            LDSM_X4_T(bv[4], bv[5], bv[6], bv[7], sV + roff + 32);
            MMA16816(oAcc[0], aP[jp], bv[0], bv[1]);
            MMA16816(oAcc[1], aP[jp], bv[2], bv[3]);
            MMA16816(oAcc[2], aP[jp], bv[4], bv[5]);
            MMA16816(oAcc[3], aP[jp], bv[6], bv[7]);
        }
        __syncthreads();
    }

    // ---- finalize + write ctx hi/lo ----
    lp0 += __shfl_xor_sync(0xffffffff, lp0, 1);
    lp0 += __shfl_xor_sync(0xffffffff, lp0, 2);
    lp1 += __shfl_xor_sync(0xffffffff, lp1, 1);
    lp1 += __shfl_xor_sync(0xffffffff, lp1, 2);
    float inv0 = 1.f / lp0, inv1 = 1.f / lp1;
    int r0 = qbase + wq * 16 + tq, r1 = r0 + 8;
    #pragma unroll
    for (int nf = 0; nf < 4; nf++) {
        int dh = 8 * nf + 2 * tt;
        size_t o0 = ((size_t)(b * NL + r0)) * ND + h * NDH + dh;
        size_t o1 = ((size_t)(b * NL + r1)) * ND + h * NDH + dh;
        float v00 = oAcc[nf][0] * inv0, v01 = oAcc[nf][1] * inv0;
        float v10 = oAcc[nf][2] * inv1, v11 = oAcc[nf][3] * inv1;
        *(uint32_t*)(gCtxHi + o0) = pack2_hi(v00, v01);
        *(uint32_t*)(gCtxLo + o0) = pack2_lo(v00, v01);
        *(uint32_t*)(gCtxHi + o1) = pack2_hi(v10, v11);
        *(uint32_t*)(gCtxLo + o1) = pack2_lo(v10, v11);
    }
}

// ---------------- launcher ----------------
extern "C" void kernel_launch(void* const* d_in, const int* in_sizes, int n_in,
                              void* d_out, int out_size) {
    const float* src       = (const float*)d_in[0];
    const unsigned char* mask = (const unsigned char*)d_in[1];
    const float* in_proj_w = (const float*)d_in[2];
    const float* in_proj_b = (const float*)d_in[3];
    const float* out_w     = (const float*)d_in[4];
    const float* out_b     = (const float*)d_in[5];
    const float* proj_w    = (const float*)d_in[6];
    const float* proj_b    = (const float*)d_in[7];
    const float* ff1_w     = (const float*)d_in[8];
    const float* ff1_b     = (const float*)d_in[9];
    const float* ff2_w     = (const float*)d_in[10];
    const float* ff2_b     = (const float*)d_in[11];
    float* out = (float*)d_out;

    cudaFuncSetAttribute(mma_gemm<0>, cudaFuncAttributeMaxDynamicSharedMemorySize, SMEM_DYN);
    cudaFuncSetAttribute(mma_gemm<1>, cudaFuncAttributeMaxDynamicSharedMemorySize, SMEM_DYN);
    cudaFuncSetAttribute(mma_gemm<2>, cudaFuncAttributeMaxDynamicSharedMemorySize, SMEM_DYN);
    cudaFuncSetAttribute(mma_gemm<3>, cudaFuncAttributeMaxDynamicSharedMemorySize, SMEM_DYN);

    float *pH, *pBc;
    __nv_bfloat16 *pSrcHi, *pSrcLo, *pCtxHi, *pCtxLo, *pHHi, *pHLo, *pFFHi, *pFFLo;
    __nv_bfloat16 *pWqkvHi, *pWqkvLo, *pWcHi, *pWcLo, *pW1Hi, *pW1Lo, *pW2Hi, *pW2Lo;
    cudaGetSymbolAddress((void**)&pH, gH);
    cudaGetSymbolAddress((void**)&pBc, gBc);
    cudaGetSymbolAddress((void**)&pSrcHi, gSrcHi);  cudaGetSymbolAddress((void**)&pSrcLo, gSrcLo);
    cudaGetSymbolAddress((void**)&pCtxHi, gCtxHi);  cudaGetSymbolAddress((void**)&pCtxLo, gCtxLo);
    cudaGetSymbolAddress((void**)&pHHi, gHHi);      cudaGetSymbolAddress((void**)&pHLo, gHLo);
    cudaGetSymbolAddress((void**)&pFFHi, gFFHi);    cudaGetSymbolAddress((void**)&pFFLo, gFFLo);
    cudaGetSymbolAddress((void**)&pWqkvHi, gWqkvHi); cudaGetSymbolAddress((void**)&pWqkvLo, gWqkvLo);
    cudaGetSymbolAddress((void**)&pWcHi, gWcHi);    cudaGetSymbolAddress((void**)&pWcLo, gWcLo);
    cudaGetSymbolAddress((void**)&pW1Hi, gW1Hi);    cudaGetSymbolAddress((void**)&pW1Lo, gW1Lo);
    cudaGetSymbolAddress((void**)&pW2Hi, gW2Hi);    cudaGetSymbolAddress((void**)&pW2Lo, gW2Lo);

    // setup
    detect_mask_kernel<<<1, 256>>>(mask);
    lengths_kernel<<<NB, 256>>>(mask);
    conv_kernel<<<(NM*ND/4 + 255)/256, 256>>>(src, pSrcHi, pSrcLo, NM*ND/4);
    conv_kernel<<<(3*ND*ND/4 + 255)/256, 256>>>(in_proj_w, pWqkvHi, pWqkvLo, 3*ND*ND/4);
    conv_kernel<<<(NDFF*ND/4 + 255)/256, 256>>>(ff1_w, pW1Hi, pW1Lo, NDFF*ND/4);
    conv_kernel<<<(ND*NDFF/4 + 255)/256, 256>>>(ff2_w, pW2Hi, pW2Lo, ND*NDFF/4);
    fuse_w_kernel<<<ND, ND>>>(proj_w, out_w);
    fuse_b_kernel<<<ND, 256>>>(proj_w, out_b, proj_b);

    // QKV = src @ in_proj_w^T + b -> bf16 Q/K/V (hi/lo)
    mma_gemm<0><<<dim3(6, 64), 256, SMEM_DYN>>>(pSrcHi, pSrcLo, pWqkvHi, pWqkvLo,
        in_proj_b, nullptr, nullptr, nullptr, nullptr, NM, 3*ND, ND);
    // tensor-core attention -> ctx hi/lo
    attn_mma_kernel<<<dim3(16, 64), 128>>>();
    // h = src + ctx @ Wc^T + bc
    mma_gemm<1><<<dim3(2, 64), 256, SMEM_DYN>>>(pCtxHi, pCtxLo, pWcHi, pWcLo,
        pBc, src, pH, pHHi, pHLo, NM, ND, ND);
    // ff = gelu(h @ ff1_w^T + b1)
    mma_gemm<2><<<dim3(16, 64), 256, SMEM_DYN>>>(pHHi, pHLo, pW1Hi, pW1Lo,
        ff1_b, nullptr, nullptr, pFFHi, pFFLo, NM, NDFF, ND);
    // out = h + ff @ ff2_w^T + b2, padded rows zeroed
    mma_gemm<3><<<dim3(2, 64), 256, SMEM_DYN>>>(pFFHi, pFFLo, pW2Hi, pW2Lo,
        ff2_b, pH, out, nullptr, nullptr, NM, ND, NDFF);
}

// round 5
// speedup vs baseline: 2.9297x; 1.1279x over previous
#include <cuda_runtime.h>
#include <cuda_bf16.h>
#include <math.h>
#include <stdint.h>

#define NB 8
#define NL 1024
#define ND 256
#define NH 8
#define NDH 32
#define NDFF 2048
#define NM (NB*NL)

// ---------------- scratch (device globals; allocation-free, zero-init) ----------------
__device__ float gH[NM*ND];
__device__ __nv_bfloat16 gQhi[64*NL*NDH], gQlo[64*NL*NDH];
__device__ __nv_bfloat16 gKhi[64*NL*NDH], gKlo[64*NL*NDH];
__device__ __nv_bfloat16 gVhi[64*NL*NDH];
__device__ __nv_bfloat16 gSrcHi[NM*ND],  gSrcLo[NM*ND];
__device__ __nv_bfloat16 gCtxHi[NM*ND],  gCtxLo[NM*ND];
__device__ __nv_bfloat16 gHHi[NM*ND],    gHLo[NM*ND];
__device__ __nv_bfloat16 gFFHi[(size_t)NM*NDFF], gFFLo[(size_t)NM*NDFF];
__device__ __nv_bfloat16 gWqkvHi[3*ND*ND], gWqkvLo[3*ND*ND];
__device__ __nv_bfloat16 gWcHi[ND*ND],     gWcLo[ND*ND];
__device__ __nv_bfloat16 gW1Hi[NDFF*ND],   gW1Lo[NDFF*ND];
__device__ __nv_bfloat16 gW2Hi[ND*NDFF],   gW2Lo[ND*NDFF];
__device__ float gBc[ND];
__device__ int   gLen[NB];

// ---------------- helpers ----------------
__device__ __forceinline__ uint32_t smem_u32(const void* p) {
    uint32_t a;
    asm("{ .reg .u64 t; cvta.to.shared.u64 t, %1; cvt.u32.u64 %0, t; }" : "=r"(a) : "l"(p));
    return a;
}
__device__ __forceinline__ void cpasync16(uint32_t saddr, const void* gaddr) {
    asm volatile("cp.async.cg.shared.global [%0], [%1], 16;" :: "r"(saddr), "l"(gaddr) : "memory");
}
#define CP_COMMIT() asm volatile("cp.async.commit_group;" ::: "memory")
#define CP_WAIT(n)  asm volatile("cp.async.wait_group %0;" :: "n"(n) : "memory")

#define LDSM_X4(r0, r1, r2, r3, addr) \
    asm volatile("ldmatrix.sync.aligned.m8n8.x4.shared.b16 {%0,%1,%2,%3}, [%4];" \
        : "=r"(r0), "=r"(r1), "=r"(r2), "=r"(r3) : "r"(addr))
#define LDSM_X4_T(r0, r1, r2, r3, addr) \
    asm volatile("ldmatrix.sync.aligned.m8n8.x4.trans.shared.b16 {%0,%1,%2,%3}, [%4];" \
        : "=r"(r0), "=r"(r1), "=r"(r2), "=r"(r3) : "r"(addr))

#define MMA16816(d, a, b0, b1) \
    asm volatile("mma.sync.aligned.m16n8k16.row.col.f32.bf16.bf16.f32 " \
        "{%0,%1,%2,%3}, {%4,%5,%6,%7}, {%8,%9}, {%0,%1,%2,%3};" \
        : "+f"((d)[0]), "+f"((d)[1]), "+f"((d)[2]), "+f"((d)[3]) \
        : "r"((a)[0]), "r"((a)[1]), "r"((a)[2]), "r"((a)[3]), "r"(b0), "r"(b1))

__device__ __forceinline__ float gelu_f(float x) {
    return 0.5f * x * (1.f + erff(x * 0.7071067811865475f));
}
__device__ __forceinline__ uint32_t pack2_hi(float a, float b) {
    __nv_bfloat16 h0 = __float2bfloat16(a), h1 = __float2bfloat16(b);
    return ((uint32_t)__bfloat16_as_ushort(h1) << 16) | __bfloat16_as_ushort(h0);
}
__device__ __forceinline__ uint32_t pack2_lo(float a, float b) {
    __nv_bfloat16 h0 = __float2bfloat16(a), h1 = __float2bfloat16(b);
    float l0 = a - __bfloat162float(h0), l1 = b - __bfloat162float(h1);
    __nv_bfloat16 g0 = __float2bfloat16(l0), g1 = __float2bfloat16(l1);
    return ((uint32_t)__bfloat16_as_ushort(g1) << 16) | __bfloat16_as_ushort(g0);
}

// ---------------- merged setup: mask mode detect + per-batch lengths ----------------
__global__ __launch_bounds__(1024) void setup_kernel(const unsigned char* __restrict__ mb) {
    __shared__ int flag;
    __shared__ int cnt[NB];
    const int tid = threadIdx.x;
    if (tid == 0) flag = 0;
    if (tid < NB) cnt[tid] = 0;
    __syncthreads();
    int f = 0;
    for (int i = tid; i < NB*NL; i += 1024)
        if ((i & 3) != 0 && mb[i] != 0) f = 1;
    if (f) atomicOr(&flag, 1);
    __syncthreads();
    const int mode = flag;
    #pragma unroll
    for (int b = 0; b < NB; b++) {
        int i = b * NL + tid;
        int pad = mode ? (mb[i] != 0) : (((const int*)mb)[i] != 0);
        unsigned vm = __ballot_sync(0xffffffff, !pad);
        if ((tid & 31) == 0) atomicAdd(&cnt[b], __popc(vm));
    }
    __syncthreads();
    if (tid < NB) gLen[tid] = cnt[tid];
}

// ---------------- merged fp32 -> bf16 hi/lo conversion (all 4 tensors) ----------------
#define CN0 (NM*ND/4)
#define CN1 (3*ND*ND/4)
#define CN2 (NDFF*ND/4)
#define CN3 (ND*NDFF/4)
__global__ void conv_all(const float* __restrict__ src, const float* __restrict__ w0,
                         const float* __restrict__ w1, const float* __restrict__ w2) {
    int i = blockIdx.x * 256 + threadIdx.x;
    const float* x; __nv_bfloat16 *hi, *lo;
    if (i < CN0)                 { x = src; hi = gSrcHi;  lo = gSrcLo; }
    else if (i < CN0+CN1)        { i -= CN0; x = w0; hi = gWqkvHi; lo = gWqkvLo; }
    else if (i < CN0+CN1+CN2)    { i -= CN0+CN1; x = w1; hi = gW1Hi; lo = gW1Lo; }
    else if (i < CN0+CN1+CN2+CN3){ i -= CN0+CN1+CN2; x = w2; hi = gW2Hi; lo = gW2Lo; }
    else return;
    float4 f = ((const float4*)x)[i];
    uint2 h, l;
    h.x = pack2_hi(f.x, f.y); h.y = pack2_hi(f.z, f.w);
    l.x = pack2_lo(f.x, f.y); l.y = pack2_lo(f.z, f.w);
    ((uint2*)hi)[i] = h;
    ((uint2*)lo)[i] = l;
}

// ---------------- merged weight+bias fusion ----------------
__global__ void fuse_wb(const float* __restrict__ pw, const float* __restrict__ ow,
                        const float* __restrict__ ob, const float* __restrict__ pb) {
    int i = blockIdx.x, j = threadIdx.x;
    if (i == ND) {  // bias block
        float s = pb[j];
        #pragma unroll 8
        for (int k = 0; k < ND; k++)
            s = fmaf(pw[j*ND + k], ob[k], s);
        gBc[j] = s;
        return;
    }
    float s = 0.f;
    #pragma unroll 8
    for (int k = 0; k < ND; k++)
        s = fmaf(pw[i*ND + k], ow[k*ND + j], s);
    __nv_bfloat16 h = __float2bfloat16(s);
    gWcHi[i*ND + j] = h;
    gWcLo[i*ND + j] = __float2bfloat16(s - __bfloat162float(h));
}

// ---------------- mma.sync split-bf16 GEMM: C[M,N] = A[M,K] @ B[N,K]^T ----------------
// 128x128x32 tile; skips fully-padded M tiles (rows >= gLen[batch]).
#define TILE_B 10240
#define STAGE_B (4*TILE_B)
#define SMEM_DYN (2*STAGE_B)

template<int EPI>
__global__ __launch_bounds__(256) void mma_gemm(
    const __nv_bfloat16* __restrict__ Ahi, const __nv_bfloat16* __restrict__ Alo,
    const __nv_bfloat16* __restrict__ Bhi, const __nv_bfloat16* __restrict__ Blo,
    const float* __restrict__ bias, const float* __restrict__ res,
    float* __restrict__ Cf, __nv_bfloat16* __restrict__ Chi, __nv_bfloat16* __restrict__ Clo,
    int M, int N, int K)
{
    extern __shared__ char sm[];
    const uint32_t sb = smem_u32(sm);
    const int tid = threadIdx.x;
    const int lane = tid & 31, wid = tid >> 5;
    const int wm = wid & 3, wn = wid >> 2;
    const int bm = blockIdx.y * 128, bn = blockIdx.x * 128;

    // ---- padding skip: tile fully beyond this batch's valid length ----
    if ((bm & (NL - 1)) >= gLen[bm >> 10]) {
        if (EPI == 3) {
            const float4 z4 = make_float4(0.f, 0.f, 0.f, 0.f);
            #pragma unroll
            for (int it = 0; it < 16; it++) {
                int u = it * 256 + tid;          // 4096 float4 = 128x128 tile
                int r = u >> 5, c = (u & 31) << 2;
                *(float4*)(Cf + (size_t)(bm + r) * N + bn + c) = z4;
            }
        }
        return;
    }

    float acc[2][8][4];
    #pragma unroll
    for (int i = 0; i < 2; i++)
        #pragma unroll
        for (int j = 0; j < 8; j++)
            #pragma unroll
            for (int c = 0; c < 4; c++) acc[i][j][c] = 0.f;

    const int nt = K >> 5;

    auto prefetch = [&](int stage, int kt) {
        const int k0 = kt << 5;
        #pragma unroll
        for (int it = 0; it < 8; it++) {
            int u = (it << 8) + tid;
            int mat = u >> 9, w = u & 511, r = w >> 2, c = w & 3;
            const __nv_bfloat16* g;
            int rb;
            if      (mat == 0) { g = Ahi; rb = bm; }
            else if (mat == 1) { g = Alo; rb = bm; }
            else if (mat == 2) { g = Bhi; rb = bn; }
            else               { g = Blo; rb = bn; }
            const void* ga = g + (size_t)(rb + r) * K + k0 + (c << 3);
            uint32_t sa = sb + (uint32_t)(stage * STAGE_B + mat * TILE_B + r * 80 + (c << 4));
            cpasync16(sa, ga);
        }
        CP_COMMIT();
    };

    auto compute = [&](int stage) {
        const uint32_t stb = sb + (uint32_t)(stage * STAGE_B);
        #pragma unroll
        for (int ks = 0; ks < 2; ks++) {
            uint32_t af[2][2][4];
            #pragma unroll
            for (int d = 0; d < 2; d++)
                #pragma unroll
                for (int fm = 0; fm < 2; fm++) {
                    int row = wm * 32 + fm * 16 + (lane & 15);
                    int chunk = ks * 2 + (lane >> 4);
                    uint32_t a = stb + (uint32_t)(d * TILE_B + row * 80 + chunk * 16);
                    LDSM_X4(af[d][fm][0], af[d][fm][1], af[d][fm][2], af[d][fm][3], a);
                }
            uint32_t bh_[4][4], bl_[4][4];
            #pragma unroll
            for (int d = 0; d < 2; d++)
                #pragma unroll
                for (int fq = 0; fq < 4; fq++) {
                    int g = lane >> 3;
                    int row = wn * 64 + fq * 16 + ((g >> 1) << 3) + (lane & 7);
                    int chunk = ks * 2 + (g & 1);
                    uint32_t a = stb + (uint32_t)((2 + d) * TILE_B + row * 80 + chunk * 16);
                    uint32_t* dst = d ? bl_[fq] : bh_[fq];
                    LDSM_X4(dst[0], dst[1], dst[2], dst[3], a);
                }
            #pragma unroll
            for (int fm = 0; fm < 2; fm++)
                #pragma unroll
                for (int fn = 0; fn < 8; fn++) {
                    uint32_t bh0 = bh_[fn >> 1][(fn & 1) * 2], bh1 = bh_[fn >> 1][(fn & 1) * 2 + 1];
                    uint32_t bl0 = bl_[fn >> 1][(fn & 1) * 2], bl1 = bl_[fn >> 1][(fn & 1) * 2 + 1];
                    MMA16816(acc[fm][fn], af[0][fm], bh0, bh1);
                    MMA16816(acc[fm][fn], af[0][fm], bl0, bl1);
                    MMA16816(acc[fm][fn], af[1][fm], bh0, bh1);
                }
        }
    };

    prefetch(0, 0);
    for (int i = 0; i < nt; i++) {
        if (i + 1 < nt) {
            prefetch((i + 1) & 1, i + 1);
            CP_WAIT(1);
        } else {
            CP_WAIT(0);
        }
        __syncthreads();
        compute(i & 1);
        __syncthreads();
    }

    // ---------------- epilogue ----------------
    const int tq = lane >> 2, tr2 = (lane & 3) << 1;
    #pragma unroll
    for (int fm = 0; fm < 2; fm++) {
        #pragma unroll
        for (int fn = 0; fn < 8; fn++) {
            int col = bn + wn * 64 + fn * 8 + tr2;
            float b0 = __ldg(bias + col), b1 = __ldg(bias + col + 1);
            #pragma unroll
            for (int half = 0; half < 2; half++) {
                int row = bm + wm * 32 + fm * 16 + tq + half * 8;
                float v0 = acc[fm][fn][half * 2]     + b0;
                float v1 = acc[fm][fn][half * 2 + 1] + b1;
                if (EPI == 0) {
                    int t = col >> 8, h = (col & 255) >> 5, dh = col & 31;
                    int bb = row >> 10, ll = row & 1023;
                    size_t o = (((size_t)(bb * NH + h)) * NL + ll) * NDH + dh;
                    uint32_t hv = pack2_hi(v0, v1), lv = pack2_lo(v0, v1);
                    if (t == 0)      { *(uint32_t*)(gQhi + o) = hv; *(uint32_t*)(gQlo + o) = lv; }
                    else if (t == 1) { *(uint32_t*)(gKhi + o) = hv; *(uint32_t*)(gKlo + o) = lv; }
                    else             { *(uint32_t*)(gVhi + o) = hv; }
                } else if (EPI == 1) {
                    size_t o = (size_t)row * N + col;
                    v0 += __ldg(res + o); v1 += __ldg(res + o + 1);
                    *(float2*)(Cf + o) = make_float2(v0, v1);
                    *(uint32_t*)(Chi + o) = pack2_hi(v0, v1);
                    *(uint32_t*)(Clo + o) = pack2_lo(v0, v1);
                } else if (EPI == 2) {
                    size_t o = (size_t)row * N + col;
                    v0 = gelu_f(v0); v1 = gelu_f(v1);
                    *(uint32_t*)(Chi + o) = pack2_hi(v0, v1);
                    *(uint32_t*)(Clo + o) = pack2_lo(v0, v1);
                } else {
                    size_t o = (size_t)row * N + col;
                    v0 += __ldg(res + o); v1 += __ldg(res + o + 1);
                    int bb = row >> 10, ll = row & 1023;
                    if (ll >= gLen[bb]) { v0 = 0.f; v1 = 0.f; }
                    *(float2*)(Cf + o) = make_float2(v0, v1);
                }
            }
        }
    }
}

// ---------------- tensor-core flash attention ----------------
#define AQ_B 5120
#define AKV_B (3*AQ_B)

__global__ __launch_bounds__(128) void attn_mma_kernel() {
    __shared__ __align__(16) unsigned char smem[2*AQ_B + 2*AKV_B];
    const uint32_t sb = smem_u32(smem);
    const uint32_t sQhi = sb, sQlo = sb + AQ_B;
    const uint32_t sKV0 = sb + 2*AQ_B;

    const int tid = threadIdx.x, lane = tid & 31, wq = tid >> 5;
    const int bh = blockIdx.y, b = bh >> 3, h = bh & 7;
    const int qbase = blockIdx.x * 64;
    const int g = lane >> 3;
    const int tq = lane >> 2, tt = lane & 3;

    const int S = gLen[b];
    if (qbase >= S) return;   // fully-padded q tile: ctx rows stay zero

    const __nv_bfloat16* Qh = gQhi + (size_t)bh * NL * NDH;
    const __nv_bfloat16* Ql = gQlo + (size_t)bh * NL * NDH;
    const __nv_bfloat16* Kh = gKhi + (size_t)bh * NL * NDH;
    const __nv_bfloat16* Kl = gKlo + (size_t)bh * NL * NDH;
    const __nv_bfloat16* Vh = gVhi + (size_t)bh * NL * NDH;

    const float sf = (float)S, invs = 1.f / sf;
    const float scale = 0.1767766952966369f;  // 1/sqrt(32)
    const int nt = (S + 63) >> 6;

    #pragma unroll
    for (int it = 0; it < 4; it++) {
        int u = (it << 7) + tid;
        int mat = u >> 8, w = u & 255, r = w >> 2, c = w & 3;
        const __nv_bfloat16* gp = mat ? Ql : Qh;
        cpasync16((mat ? sQlo : sQhi) + (uint32_t)(r * 80 + (c << 4)),
                  gp + (size_t)(qbase + r) * NDH + (c << 3));
    }
    auto loadKV = [&](int stage, int kt) {
        uint32_t base = sKV0 + (uint32_t)stage * AKV_B;
        #pragma unroll
        for (int it = 0; it < 6; it++) {
            int u = (it << 7) + tid;
            int mat = u >> 8, w = u & 255, r = w >> 2, c = w & 3;
            const __nv_bfloat16* gp = (mat == 0) ? Kh : (mat == 1) ? Kl : Vh;
            cpasync16(base + (uint32_t)(mat * AQ_B + r * 80 + (c << 4)),
                      gp + (size_t)(kt + r) * NDH + (c << 3));
        }
        CP_COMMIT();
    };
    loadKV(0, 0);

    uint32_t aQh[2][4], aQl[2][4];
    float oAcc[4][4];
    #pragma unroll
    for (int i = 0; i < 4; i++)
        #pragma unroll
        for (int j = 0; j < 4; j++) oAcc[i][j] = 0.f;
    float mrow0 = -1e30f, mrow1 = -1e30f, lp0 = 0.f, lp1 = 0.f;

    const float qr0 = (float)(qbase + wq * 16 + tq);
    const float qr1 = qr0 + 8.f;

    for (int i = 0; i < nt; i++) {
        if (i + 1 < nt) { loadKV((i + 1) & 1, (i + 1) << 6); CP_WAIT(1); }
        else            { CP_WAIT(0); }
        __syncthreads();

        if (i == 0) {
            #pragma unroll
            for (int ks = 0; ks < 2; ks++) {
                uint32_t roff = (uint32_t)((wq * 16 + ((g & 1) << 3) + (lane & 7)) * 80
                                           + 32 * ks + 16 * (g >> 1));
                LDSM_X4(aQh[ks][0], aQh[ks][1], aQh[ks][2], aQh[ks][3], sQhi + roff);
                LDSM_X4(aQl[ks][0], aQl[ks][1], aQl[ks][2], aQl[ks][3], sQlo + roff);
            }
        }

        const uint32_t sK  = sKV0 + (uint32_t)(i & 1) * AKV_B;
        const uint32_t sKl = sK + AQ_B;
        const uint32_t sV  = sK + 2 * AQ_B;
        const int kt = i << 6;

        float sA[8][4];
        #pragma unroll
        for (int j = 0; j < 8; j++)
            #pragma unroll
            for (int c = 0; c < 4; c++) sA[j][c] = 0.f;

        #pragma unroll
        for (int ks = 0; ks < 2; ks++) {
            #pragma unroll
            for (int jp = 0; jp < 4; jp++) {
                uint32_t kh[4], kl[4];
                uint32_t roff = (uint32_t)((16 * jp + ((g >> 1) << 3) + (lane & 7)) * 80
                                           + 32 * ks + 16 * (g & 1));
                LDSM_X4(kh[0], kh[1], kh[2], kh[3], sK + roff);
                LDSM_X4(kl[0], kl[1], kl[2], kl[3], sKl + roff);
                MMA16816(sA[2*jp],     aQh[ks], kh[0], kh[1]);
                MMA16816(sA[2*jp],     aQl[ks], kh[0], kh[1]);
                MMA16816(sA[2*jp],     aQh[ks], kl[0], kl[1]);
                MMA16816(sA[2*jp + 1], aQh[ks], kh[2], kh[3]);
                MMA16816(sA[2*jp + 1], aQl[ks], kh[2], kh[3]);
                MMA16816(sA[2*jp + 1], aQh[ks], kl[2], kl[3]);
            }
        }

        float x[8][4];
        float tmax0 = -1e30f, tmax1 = -1e30f;
        #pragma unroll
        for (int j = 0; j < 8; j++) {
            int kc = kt + 8 * j + 2 * tt;
            float k0f = (float)kc, k1f = k0f + 1.f;
            float b00 = (kc     < S) ? (sf - fabsf(qr0 - k0f)) * invs : -1e30f;
            float b01 = (kc + 1 < S) ? (sf - fabsf(qr0 - k1f)) * invs : -1e30f;
            float b10 = (kc     < S) ? (sf - fabsf(qr1 - k0f)) * invs : -1e30f;
            float b11 = (kc + 1 < S) ? (sf - fabsf(qr1 - k1f)) * invs : -1e30f;
            x[j][0] = fmaf(sA[j][0], scale, b00);
            x[j][1] = fmaf(sA[j][1], scale, b01);
            x[j][2] = fmaf(sA[j][2], scale, b10);
            x[j][3] = fmaf(sA[j][3], scale, b11);
            tmax0 = fmaxf(tmax0, fmaxf(x[j][0], x[j][1]));
            tmax1 = fmaxf(tmax1, fmaxf(x[j][2], x[j][3]));
        }
        tmax0 = fmaxf(tmax0, __shfl_xor_sync(0xffffffff, tmax0, 1));
        tmax0 = fmaxf(tmax0, __shfl_xor_sync(0xffffffff, tmax0, 2));
        tmax1 = fmaxf(tmax1, __shfl_xor_sync(0xffffffff, tmax1, 1));
        tmax1 = fmaxf(tmax1, __shfl_xor_sync(0xffffffff, tmax1, 2));
        float mn0 = fmaxf(mrow0, tmax0), mn1 = fmaxf(mrow1, tmax1);
        float corr0 = __expf(mrow0 - mn0), corr1 = __expf(mrow1 - mn1);
        mrow0 = mn0; mrow1 = mn1;
        lp0 *= corr0; lp1 *= corr1;
        #pragma unroll
        for (int nf = 0; nf < 4; nf++) {
            oAcc[nf][0] *= corr0; oAcc[nf][1] *= corr0;
            oAcc[nf][2] *= corr1; oAcc[nf][3] *= corr1;
        }

        uint32_t aP[4][4];
        #pragma unroll
        for (int j = 0; j < 8; j++) {
            float p0 = __expf(x[j][0] - mn0), p1 = __expf(x[j][1] - mn0);
            float p2 = __expf(x[j][2] - mn1), p3 = __expf(x[j][3] - mn1);
            lp0 += p0 + p1; lp1 += p2 + p3;
            int jp = j >> 1, s2 = (j & 1) << 1;
            aP[jp][s2]     = pack2_hi(p0, p1);
            aP[jp][s2 + 1] = pack2_hi(p2, p3);
        }

        #pragma unroll
        for (int jp = 0; jp < 4; jp++) {
            uint32_t bv[8];
            uint32_t roff = (uint32_t)((16 * jp + ((g & 1) << 3) + (lane & 7)) * 80
                                       + 16 * (g >> 1));
            LDSM_X4_T(bv[0], bv[1], bv[2], bv[3], sV + roff);
            LDSM_X4_T(bv[4], bv[5], bv[6], bv[7], sV + roff + 32);
            MMA16816(oAcc[0], aP[jp], bv[0], bv[1]);
            MMA16816(oAcc[1], aP[jp], bv[2], bv[3]);
            MMA16816(oAcc[2], aP[jp], bv[4], bv[5]);
            MMA16816(oAcc[3], aP[jp], bv[6], bv[7]);
        }
        __syncthreads();
    }

    lp0 += __shfl_xor_sync(0xffffffff, lp0, 1);
    lp0 += __shfl_xor_sync(0xffffffff, lp0, 2);
    lp1 += __shfl_xor_sync(0xffffffff, lp1, 1);
    lp1 += __shfl_xor_sync(0xffffffff, lp1, 2);
    float inv0 = 1.f / lp0, inv1 = 1.f / lp1;
    int r0 = qbase + wq * 16 + tq, r1 = r0 + 8;
    #pragma unroll
    for (int nf = 0; nf < 4; nf++) {
        int dh = 8 * nf + 2 * tt;
        size_t o0 = ((size_t)(b * NL + r0)) * ND + h * NDH + dh;
        size_t o1 = ((size_t)(b * NL + r1)) * ND + h * NDH + dh;
        float v00 = oAcc[nf][0] * inv0, v01 = oAcc[nf][1] * inv0;
        float v10 = oAcc[nf][2] * inv1, v11 = oAcc[nf][3] * inv1;
        *(uint32_t*)(gCtxHi + o0) = pack2_hi(v00, v01);
        *(uint32_t*)(gCtxLo + o0) = pack2_lo(v00, v01);
        *(uint32_t*)(gCtxHi + o1) = pack2_hi(v10, v11);
        *(uint32_t*)(gCtxLo + o1) = pack2_lo(v10, v11);
    }
}

// ---------------- launcher ----------------
extern "C" void kernel_launch(void* const* d_in, const int* in_sizes, int n_in,
                              void* d_out, int out_size) {
    const float* src       = (const float*)d_in[0];
    const unsigned char* mask = (const unsigned char*)d_in[1];
    const float* in_proj_w = (const float*)d_in[2];
    const float* in_proj_b = (const float*)d_in[3];
    const float* out_w     = (const float*)d_in[4];
    const float* out_b     = (const float*)d_in[5];
    const float* proj_w    = (const float*)d_in[6];
    const float* proj_b    = (const float*)d_in[7];
    const float* ff1_w     = (const float*)d_in[8];
    const float* ff1_b     = (const float*)d_in[9];
    const float* ff2_w     = (const float*)d_in[10];
    const float* ff2_b     = (const float*)d_in[11];
    float* out = (float*)d_out;

    cudaFuncSetAttribute(mma_gemm<0>, cudaFuncAttributeMaxDynamicSharedMemorySize, SMEM_DYN);
    cudaFuncSetAttribute(mma_gemm<1>, cudaFuncAttributeMaxDynamicSharedMemorySize, SMEM_DYN);
    cudaFuncSetAttribute(mma_gemm<2>, cudaFuncAttributeMaxDynamicSharedMemorySize, SMEM_DYN);
    cudaFuncSetAttribute(mma_gemm<3>, cudaFuncAttributeMaxDynamicSharedMemorySize, SMEM_DYN);

    float *pH, *pBc;
    __nv_bfloat16 *pSrcHi, *pSrcLo, *pCtxHi, *pCtxLo, *pHHi, *pHLo, *pFFHi, *pFFLo;
    __nv_bfloat16 *pWqkvHi, *pWqkvLo, *pWcHi, *pWcLo, *pW1Hi, *pW1Lo, *pW2Hi, *pW2Lo;
    cudaGetSymbolAddress((void**)&pH, gH);
    cudaGetSymbolAddress((void**)&pBc, gBc);
    cudaGetSymbolAddress((void**)&pSrcHi, gSrcHi);  cudaGetSymbolAddress((void**)&pSrcLo, gSrcLo);
    cudaGetSymbolAddress((void**)&pCtxHi, gCtxHi);  cudaGetSymbolAddress((void**)&pCtxLo, gCtxLo);
    cudaGetSymbolAddress((void**)&pHHi, gHHi);      cudaGetSymbolAddress((void**)&pHLo, gHLo);
    cudaGetSymbolAddress((void**)&pFFHi, gFFHi);    cudaGetSymbolAddress((void**)&pFFLo, gFFLo);
    cudaGetSymbolAddress((void**)&pWqkvHi, gWqkvHi); cudaGetSymbolAddress((void**)&pWqkvLo, gWqkvLo);
    cudaGetSymbolAddress((void**)&pWcHi, gWcHi);    cudaGetSymbolAddress((void**)&pWcLo, gWcLo);
    cudaGetSymbolAddress((void**)&pW1Hi, gW1Hi);    cudaGetSymbolAddress((void**)&pW1Lo, gW1Lo);
    cudaGetSymbolAddress((void**)&pW2Hi, gW2Hi);    cudaGetSymbolAddress((void**)&pW2Lo, gW2Lo);

    // merged setup: 3 launches instead of 8
    setup_kernel<<<1, 1024>>>(mask);
    conv_all<<<(CN0+CN1+CN2+CN3 + 255)/256, 256>>>(src, in_proj_w, ff1_w, ff2_w);
    fuse_wb<<<ND + 1, ND>>>(proj_w, out_w, out_b, proj_b);

    // QKV = src @ in_proj_w^T + b -> bf16 Q/K/V (hi/lo)
    mma_gemm<0><<<dim3(6, 64), 256, SMEM_DYN>>>(pSrcHi, pSrcLo, pWqkvHi, pWqkvLo,
        in_proj_b, nullptr, nullptr, nullptr, nullptr, NM, 3*ND, ND);
    // tensor-core attention -> ctx hi/lo
    attn_mma_kernel<<<dim3(16, 64), 128>>>();
    // h = src + ctx @ Wc^T + bc
    mma_gemm<1><<<dim3(2, 64), 256, SMEM_DYN>>>(pCtxHi, pCtxLo, pWcHi, pWcLo,
        pBc, src, pH, pHHi, pHLo, NM, ND, ND);
    // ff = gelu(h @ ff1_w^T + b1)
    mma_gemm<2><<<dim3(16, 64), 256, SMEM_DYN>>>(pHHi, pHLo, pW1Hi, pW1Lo,
        ff1_b, nullptr, nullptr, pFFHi, pFFLo, NM, NDFF, ND);
    // out = h + ff @ ff2_w^T + b2, padded rows zeroed
    mma_gemm<3><<<dim3(2, 64), 256, SMEM_DYN>>>(pFFHi, pFFLo, pW2Hi, pW2Lo,
        ff2_b, pH, out, nullptr, nullptr, NM, ND, NDFF);
}